// round 4
// baseline (speedup 1.0000x reference)
#include <cuda_runtime.h>
#include <cuda_bf16.h>

// BERTLatticeEmbedding: ragged segment mean-pool.
// hidden [B,S,H] f32, word_ids [B,S] int32 (sorted non-decreasing per row),
// out    [B,T,H] f32: out[b,w,:] = mean of pieces with word_ids[b,s]==w (0 if none).
// B=64, S=512, H=768, T=400.
//
// R3: half-word tasks. Block = (b, 16-word tile), 128 threads. Each warp
// processes 8 half-words (3 float4 chunks each) -> ~40 regs/thread so ~12
// blocks/SM resident: whole 1600-block grid fits in ONE wave.

#define B_DIM 64
#define S_DIM 512
#define H_DIM 768
#define T_DIM 400
#define H4    (H_DIM / 4)        // 192 float4 per row
#define TILE_W 16
#define WPB    4
#define THREADS (WPB * 32)       // 128
#define NTILES (T_DIM / TILE_W)  // 25
#define NTASKS (TILE_W * 2)      // 32 half-word tasks per block
#define HALF4  (H4 / 2)          // 96 float4 per half-row

__global__ __launch_bounds__(THREADS) void pool_kernel(
    const float* __restrict__ hidden,
    const int* __restrict__ word_ids,
    float* __restrict__ out)
{
    __shared__ int s_row[S_DIM];
    __shared__ int s_start[TILE_W + 1];

    const int b     = blockIdx.y;
    const int wbase = blockIdx.x * TILE_W;
    const int tid   = threadIdx.x;

    // Cache this sample's word_ids row (2 KB) in SMEM.
    const int* __restrict__ grow = word_ids + b * S_DIM;
    #pragma unroll
    for (int i = tid; i < S_DIM; i += THREADS) s_row[i] = grow[i];
    __syncthreads();

    // Segment boundaries: s_start[i] = lower_bound(wbase + i).
    if (tid <= TILE_W) {
        const int target = wbase + tid;
        int lo = 0, hi = S_DIM;
        while (lo < hi) {
            int mid = (lo + hi) >> 1;
            if (s_row[mid] < target) lo = mid + 1; else hi = mid;
        }
        s_start[tid] = lo;
    }
    __syncthreads();

    const int warp = tid >> 5;
    const int lane = tid & 31;

    const float4* __restrict__ hin =
        reinterpret_cast<const float4*>(hidden + (size_t)b * S_DIM * H_DIM);

    #pragma unroll
    for (int t = warp; t < NTASKS; t += WPB) {
        const int wi   = t >> 1;          // word index within tile
        const int half = t & 1;           // which half of the row
        const int st   = s_start[wi];
        const int en   = s_start[wi + 1];
        const int off  = half * HALF4 + lane;   // float4 offset within row

        float4 a0 = make_float4(0.f, 0.f, 0.f, 0.f);
        float4 a1 = a0, a2 = a0;

        for (int s = st; s < en; ++s) {
            const float4* __restrict__ p = hin + (size_t)s * H4 + off;
            float4 v0 = p[0];
            float4 v1 = p[32];
            float4 v2 = p[64];
            a0.x += v0.x; a0.y += v0.y; a0.z += v0.z; a0.w += v0.w;
            a1.x += v1.x; a1.y += v1.y; a1.z += v1.z; a1.w += v1.w;
            a2.x += v2.x; a2.y += v2.y; a2.z += v2.z; a2.w += v2.w;
        }

        const int cnt = en - st;
        const float inv = 1.0f / (float)(cnt > 0 ? cnt : 1);
        a0.x *= inv; a0.y *= inv; a0.z *= inv; a0.w *= inv;
        a1.x *= inv; a1.y *= inv; a1.z *= inv; a1.w *= inv;
        a2.x *= inv; a2.y *= inv; a2.z *= inv; a2.w *= inv;

        float4* __restrict__ op =
            reinterpret_cast<float4*>(out + ((size_t)b * T_DIM + wbase + wi) * H_DIM) + off;
        op[0]  = a0;
        op[32] = a1;
        op[64] = a2;
    }
}

extern "C" void kernel_launch(void* const* d_in, const int* in_sizes, int n_in,
                              void* d_out, int out_size)
{
    const float* hidden   = (const float*)d_in[0];
    const int*   word_ids = (const int*)d_in[1];
    float* out = (float*)d_out;

    dim3 grid(NTILES, B_DIM);
    pool_kernel<<<grid, THREADS>>>(hidden, word_ids, out);
}

// round 5
// speedup vs baseline: 1.1123x; 1.1123x over previous
#include <cuda_runtime.h>
#include <cuda_bf16.h>

// BERTLatticeEmbedding: ragged segment mean-pool.
// hidden [B,S,H] f32, word_ids [B,S] int32 (sorted per row),
// out [B,T,H] f32. B=64, S=512, H=768, T=400.
//
// R4: two-kernel design.
//  K1: per-(b,w) segment bounds {start,cnt} -> __device__ scratch (200KB).
//  K2: flat warp-per-(word,half-row) streaming pool. No smem/syncs, fast
//      paths for cnt 1/2 with all loads issued before any consumption.

#define B_DIM 64
#define S_DIM 512
#define H_DIM 768
#define T_DIM 400
#define H4    (H_DIM / 4)     // 192 float4 per row
#define HALF4 (H4 / 2)        // 96 float4 per half-row

__device__ int2 g_bounds[B_DIM * T_DIM];

__global__ __launch_bounds__(256) void bounds_kernel(
    const int* __restrict__ word_ids)
{
    const int idx = blockIdx.x * 256 + threadIdx.x;   // 0 .. B*T-1
    if (idx >= B_DIM * T_DIM) return;
    const int b = idx / T_DIM;
    const int w = idx - b * T_DIM;

    const int* __restrict__ row = word_ids + b * S_DIM;

    int lo = 0, hi = S_DIM;
    while (lo < hi) {
        int mid = (lo + hi) >> 1;
        if (__ldg(row + mid) < w) lo = mid + 1; else hi = mid;
    }
    const int start = lo;

    hi = S_DIM;
    while (lo < hi) {
        int mid = (lo + hi) >> 1;
        if (__ldg(row + mid) < w + 1) lo = mid + 1; else hi = mid;
    }
    g_bounds[idx] = make_int2(start, lo - start);
}

__device__ __forceinline__ void f4add(float4& a, const float4 v) {
    a.x += v.x; a.y += v.y; a.z += v.z; a.w += v.w;
}

__global__ __launch_bounds__(256) void pool_kernel(
    const float* __restrict__ hidden,
    float* __restrict__ out)
{
    // warp task: t in [0, T*2) for sample b = blockIdx.y
    const int warp = threadIdx.x >> 5;
    const int lane = threadIdx.x & 31;
    const int t    = blockIdx.x * 8 + warp;           // 100 blocks * 8 warps = 800
    const int b    = blockIdx.y;
    const int w    = t >> 1;
    const int half = t & 1;
    const int off  = half * HALF4 + lane;

    const int2 bc  = __ldg(&g_bounds[b * T_DIM + w]);
    const int  st  = bc.x;
    const int  cnt = bc.y;

    float4* __restrict__ op =
        reinterpret_cast<float4*>(out + ((size_t)b * T_DIM + w) * H_DIM) + off;

    const float4* __restrict__ p =
        reinterpret_cast<const float4*>(hidden + (size_t)b * S_DIM * H_DIM)
        + (size_t)st * H4 + off;

    if (cnt == 0) {
        const float4 z = make_float4(0.f, 0.f, 0.f, 0.f);
        __stcs(op,      z);
        __stcs(op + 32, z);
        __stcs(op + 64, z);
        return;
    }
    if (cnt == 1) {
        float4 v0 = __ldcs(p);
        float4 v1 = __ldcs(p + 32);
        float4 v2 = __ldcs(p + 64);
        __stcs(op,      v0);
        __stcs(op + 32, v1);
        __stcs(op + 64, v2);
        return;
    }
    if (cnt == 2) {
        float4 a0 = __ldcs(p);
        float4 a1 = __ldcs(p + 32);
        float4 a2 = __ldcs(p + 64);
        float4 b0 = __ldcs(p + H4);
        float4 b1 = __ldcs(p + H4 + 32);
        float4 b2 = __ldcs(p + H4 + 64);
        f4add(a0, b0); f4add(a1, b1); f4add(a2, b2);
        a0.x *= 0.5f; a0.y *= 0.5f; a0.z *= 0.5f; a0.w *= 0.5f;
        a1.x *= 0.5f; a1.y *= 0.5f; a1.z *= 0.5f; a1.w *= 0.5f;
        a2.x *= 0.5f; a2.y *= 0.5f; a2.z *= 0.5f; a2.w *= 0.5f;
        __stcs(op,      a0);
        __stcs(op + 32, a1);
        __stcs(op + 64, a2);
        return;
    }

    // General case: pairwise to keep >=6 loads in flight.
    float4 a0 = make_float4(0.f, 0.f, 0.f, 0.f);
    float4 a1 = a0, a2 = a0;
    int s = 0;
    for (; s + 1 < cnt; s += 2) {
        const float4* q = p + (size_t)s * H4;
        float4 v0 = __ldcs(q);
        float4 v1 = __ldcs(q + 32);
        float4 v2 = __ldcs(q + 64);
        float4 u0 = __ldcs(q + H4);
        float4 u1 = __ldcs(q + H4 + 32);
        float4 u2 = __ldcs(q + H4 + 64);
        f4add(a0, v0); f4add(a1, v1); f4add(a2, v2);
        f4add(a0, u0); f4add(a1, u1); f4add(a2, u2);
    }
    if (s < cnt) {
        const float4* q = p + (size_t)s * H4;
        float4 v0 = __ldcs(q);
        float4 v1 = __ldcs(q + 32);
        float4 v2 = __ldcs(q + 64);
        f4add(a0, v0); f4add(a1, v1); f4add(a2, v2);
    }
    const float inv = 1.0f / (float)cnt;
    a0.x *= inv; a0.y *= inv; a0.z *= inv; a0.w *= inv;
    a1.x *= inv; a1.y *= inv; a1.z *= inv; a1.w *= inv;
    a2.x *= inv; a2.y *= inv; a2.z *= inv; a2.w *= inv;
    __stcs(op,      a0);
    __stcs(op + 32, a1);
    __stcs(op + 64, a2);
}

extern "C" void kernel_launch(void* const* d_in, const int* in_sizes, int n_in,
                              void* d_out, int out_size)
{
    const float* hidden   = (const float*)d_in[0];
    const int*   word_ids = (const int*)d_in[1];
    float* out = (float*)d_out;

    bounds_kernel<<<(B_DIM * T_DIM + 255) / 256, 256>>>(word_ids);

    dim3 grid(T_DIM * 2 / 8, B_DIM);   // 100 x 64 blocks, 8 warps each
    pool_kernel<<<grid, 256>>>(hidden, out);
}